// round 7
// baseline (speedup 1.0000x reference)
#include <cuda_runtime.h>
#include <cstdint>

#define NB 32        // batch
#define NS 8192      // seq len
#define ND 32        // hidden dim
#define NG 128       // 4*ND gates
#define NC 256       // output cats
#define CHUNK 32     // steps per progress publish
#define NCHUNK (NS / CHUNK)        // 256
#define NWORK 116                  // worker blocks (148 - 32)
#define NITEM (NB * NCHUNK)        // 8192 work items

// h history (B, S, D) fp32 = 33.5 MB + progress flags
__device__ float g_hs[NB * NS * ND];
__device__ int   g_prog[NB];

__device__ __forceinline__ float tanh_fast(float x) {
    float y;
    asm("tanh.approx.f32 %0, %1;" : "=f"(y) : "f"(x));
    return y;
}
__device__ __forceinline__ uint64_t pack2(float lo, float hi) {
    uint64_t r;
    asm("mov.b64 %0, {%1, %2};" : "=l"(r) : "f"(lo), "f"(hi));
    return r;
}
__device__ __forceinline__ void unpack2(float& lo, float& hi, uint64_t v) {
    asm("mov.b64 {%0, %1}, %2;" : "=f"(lo), "=f"(hi) : "l"(v));
}
__device__ __forceinline__ void fma2(uint64_t& acc, uint64_t a, uint64_t b) {
    asm("fma.rn.f32x2 %0, %1, %2, %0;" : "+l"(acc) : "l"(a), "l"(b));
}
__device__ __forceinline__ uint64_t add2(uint64_t a, uint64_t b) {
    uint64_t r;
    asm("add.rn.f32x2 %0, %1, %2;" : "=l"(r) : "l"(a), "l"(b));
    return r;
}
__device__ __forceinline__ uint32_t smem_u32(const void* p) {
    uint32_t a;
    asm("{ .reg .u64 t; cvta.to.shared.u64 t, %1; cvt.u32.u64 %0, t; }"
        : "=r"(a) : "l"(p));
    return a;
}

__global__ void init_kernel() {
    if (threadIdx.x < NB) g_prog[threadIdx.x] = 0;
}

// grid = 148 x 128.
//   blocks 0..31: LSTM scan — SINGLE warp (warp 0), lane = hidden dim, each lane
//     computes ALL four gate columns -> no barrier, no cross-warp exchange.
//     h broadcast via same-warp smem round trip (in-order LSU, validated R5).
//   blocks 32..147: persistent epilogue workers (unchanged, fully hidden).
__global__ void __launch_bounds__(128, 1) fused_kernel(
    const float* __restrict__ x,      // (B, S)
    const float* __restrict__ bos,    // (D)
    const float* __restrict__ W_in,   // (1, D)
    const float* __restrict__ b_in,   // (D)
    const float* __restrict__ Wx,     // (D, 4D)
    const float* __restrict__ Wh,     // (D, 4D)
    const float* __restrict__ b_lstm, // (4D)
    const float* __restrict__ W_out,  // (D, C)
    const float* __restrict__ b_out,  // (C)
    float* __restrict__ out)          // (B, S, C)
{
    const int bid = blockIdx.x;
    const int tid = threadIdx.x;

    if (bid < NB) {
        // ───────────────────────── scan block (warp 0 only) ─────────────────────────
        if (tid >= 32) return;
        const int b = bid;
        const int l = tid;                   // lane = hidden dim

        __shared__ float hbuf[ND];           // h exchange row (same-warp RAW)

        // all four gate columns' Wh in registers (sigmoid gates pre-scaled 0.5)
        uint64_t whp[4][16];
        float u[4], v[4], zb[4];
#pragma unroll
        for (int g = 0; g < 4; g++) {
            const float ws  = (g == 2) ? 1.0f : 0.5f;
            const int   col = g * 32 + l;
#pragma unroll
            for (int j = 0; j < 16; j++)
                whp[g][j] = pack2(ws * Wh[(2 * j) * NG + col],
                                  ws * Wh[(2 * j + 1) * NG + col]);
            float uu = 0.f, vv = 0.f, z0 = 0.f;
            for (int d = 0; d < ND; d++) {
                float wx = Wx[d * NG + col];
                uu = fmaf(W_in[d], wx, uu);
                vv = fmaf(b_in[d], wx, vv);
                z0 = fmaf(bos[d],  wx, z0);
            }
            float bl = b_lstm[col];
            u[g]  = ws * uu;
            v[g]  = ws * (vv + bl);
            zb[g] = ws * (z0 + bl);
        }

        const uint32_t haddr = smem_u32(hbuf);
        asm volatile("st.shared.f32 [%0], %1;"
                     :: "r"(haddr + l * 4), "f"(0.f) : "memory");
        __syncwarp();

        float c = 0.f;
        const float* xb = x + (size_t)b * NS;
        float* hs_b = g_hs + (size_t)b * NS * ND + l;

        for (int n = 0; n < NCHUNK; n++) {
            const int s0 = n * CHUNK;
            const float xv = __ldg(xb + s0 + l);    // chunk's x in lane regs
#pragma unroll 8
            for (int jj = 0; jj < CHUNK; jj++) {
                float xn = __shfl_sync(0xffffffffu, xv, jj);

                uint64_t hp[16];
#pragma unroll
                for (int j = 0; j < 8; j++)
                    asm volatile("ld.shared.v2.u64 {%0,%1}, [%2];"
                                 : "=l"(hp[2 * j]), "=l"(hp[2 * j + 1])
                                 : "r"(haddr + j * 16));

                // gate order g, i, f, o so tanh(g)/sigma(i) are ready early
                uint64_t g0 = pack2(zb[2], 0.f), g1 = pack2(0.f, 0.f);
                uint64_t i0 = pack2(zb[0], 0.f), i1 = pack2(0.f, 0.f);
                uint64_t f0 = pack2(zb[1], 0.f), f1 = pack2(0.f, 0.f);
                uint64_t o0 = pack2(zb[3], 0.f), o1 = pack2(0.f, 0.f);
#pragma unroll
                for (int j = 0; j < 8; j++) {
                    fma2(g0, hp[2 * j],     whp[2][2 * j]);
                    fma2(g1, hp[2 * j + 1], whp[2][2 * j + 1]);
                }
#pragma unroll
                for (int j = 0; j < 8; j++) {
                    fma2(i0, hp[2 * j],     whp[0][2 * j]);
                    fma2(i1, hp[2 * j + 1], whp[0][2 * j + 1]);
                }
#pragma unroll
                for (int j = 0; j < 8; j++) {
                    fma2(f0, hp[2 * j],     whp[1][2 * j]);
                    fma2(f1, hp[2 * j + 1], whp[1][2 * j + 1]);
                }
#pragma unroll
                for (int j = 0; j < 8; j++) {
                    fma2(o0, hp[2 * j],     whp[3][2 * j]);
                    fma2(o1, hp[2 * j + 1], whp[3][2 * j + 1]);
                }
                float lo, hi, zg, zi, zf, zo;
                unpack2(lo, hi, add2(g0, g1)); zg = lo + hi;
                unpack2(lo, hi, add2(i0, i1)); zi = lo + hi;
                unpack2(lo, hi, add2(f0, f1)); zf = lo + hi;
                unpack2(lo, hi, add2(o0, o1)); zo = lo + hi;

                float tg = tanh_fast(zg);
                float i_ = fmaf(0.5f, tanh_fast(zi), 0.5f);
                float f_ = fmaf(0.5f, tanh_fast(zf), 0.5f);
                float o_ = fmaf(0.5f, tanh_fast(zo), 0.5f);

                float p = i_ * tg;                   // overlaps f/o dots
                c = fmaf(f_, c, p);
                float h = o_ * tanh_fast(c);

                asm volatile("st.shared.f32 [%0], %1;"
                             :: "r"(haddr + l * 4), "f"(h) : "memory");
                hs_b[(size_t)(s0 + jj) * ND] = h;

                zb[0] = fmaf(xn, u[0], v[0]);
                zb[1] = fmaf(xn, u[1], v[1]);
                zb[2] = fmaf(xn, u[2], v[2]);
                zb[3] = fmaf(xn, u[3], v[3]);
            }
            if (l == 0) {
                __threadfence();                     // chunk's h STGs visible
                asm volatile("st.global.release.gpu.s32 [%0], %1;"
                             :: "l"(&g_prog[b]), "r"(n + 1) : "memory");
            }
        }
    } else {
        // ─────────────────────── worker block (unchanged) ───────────────────────
        const int wkr = bid - NB;
        __shared__ float tile[CHUNK * ND];           // 4 KB h tile

        const int c0 = tid, c1 = tid + 128;
        uint64_t wv0[16], wv1[16];
#pragma unroll
        for (int j = 0; j < 16; j++) {
            wv0[j] = pack2(W_out[(2 * j) * NC + c0], W_out[(2 * j + 1) * NC + c0]);
            wv1[j] = pack2(W_out[(2 * j) * NC + c1], W_out[(2 * j + 1) * NC + c1]);
        }
        const float bias0 = b_out[c0], bias1 = b_out[c1];

        for (int i = wkr; i < NITEM; i += NWORK) {
            const int b     = i & (NB - 1);
            const int chunk = i >> 5;

            if (tid == 0) {
                int cur;
                do {
                    asm volatile("ld.acquire.gpu.global.s32 %0, [%1];"
                                 : "=r"(cur) : "l"(&g_prog[b]) : "memory");
                    if (cur > chunk) break;
                    __nanosleep(128);
                } while (true);
            }
            __syncthreads();                         // flag acquire -> tile loads

            const float* src = g_hs + ((size_t)b * NS + (size_t)chunk * CHUNK) * ND;
#pragma unroll
            for (int q = 0; q < 2; q++)
                ((float4*)tile)[tid + 128 * q] = ((const float4*)src)[tid + 128 * q];
            __syncthreads();

            float* orow = out + ((size_t)b * NS + (size_t)chunk * CHUNK) * NC;
#pragma unroll 2
            for (int r = 0; r < CHUNK; r++) {
                const ulonglong2* hr = (const ulonglong2*)(tile + r * ND);
                uint64_t p0 = pack2(bias0, 0.f), p1 = pack2(0.f, 0.f);
                uint64_t q0 = pack2(bias1, 0.f), q1 = pack2(0.f, 0.f);
#pragma unroll
                for (int j = 0; j < 8; j++) {
                    ulonglong2 hv = hr[j];
                    fma2(p0, hv.x, wv0[2 * j]);
                    fma2(p1, hv.y, wv0[2 * j + 1]);
                    fma2(q0, hv.x, wv1[2 * j]);
                    fma2(q1, hv.y, wv1[2 * j + 1]);
                }
                float lo, hi, r0, r1;
                unpack2(lo, hi, add2(p0, p1)); r0 = lo + hi;
                unpack2(lo, hi, add2(q0, q1)); r1 = lo + hi;
                orow[(size_t)r * NC + c0] = r0;
                orow[(size_t)r * NC + c1] = r1;
            }
            __syncthreads();                         // tile reuse guard
        }
    }
}

extern "C" void kernel_launch(void* const* d_in, const int* in_sizes, int n_in,
                              void* d_out, int out_size)
{
    const float* x      = (const float*)d_in[0];
    const float* bos    = (const float*)d_in[1];
    const float* W_in   = (const float*)d_in[2];
    const float* b_in   = (const float*)d_in[3];
    const float* Wx     = (const float*)d_in[4];
    const float* Wh     = (const float*)d_in[5];
    const float* b_lstm = (const float*)d_in[6];
    const float* W_out  = (const float*)d_in[7];
    const float* b_out  = (const float*)d_in[8];

    init_kernel<<<1, 32>>>();
    fused_kernel<<<148, 128>>>(x, bos, W_in, b_in, Wx, Wh, b_lstm,
                               W_out, b_out, (float*)d_out);
}

// round 8
// speedup vs baseline: 1.2767x; 1.2767x over previous
#include <cuda_runtime.h>
#include <cstdint>

#define NB 32        // batch
#define NS 8192      // seq len
#define ND 32        // hidden dim
#define NG 128       // 4*ND gates
#define NC 256       // output cats
#define CHUNK 32     // steps per progress publish
#define NCHUNK (NS / CHUNK)        // 256
#define NWORK 116                  // worker blocks (148 - 32)
#define NITEM (NB * NCHUNK)        // 8192 work items
#define NT 160                     // threads per block (5 warps in scan blocks)

// h history (B, S, D) fp32 = 33.5 MB + progress flags
__device__ float g_hs[NB * NS * ND];
__device__ int   g_prog[NB];

__device__ __forceinline__ float tanh_fast(float x) {
    float y;
    asm("tanh.approx.f32 %0, %1;" : "=f"(y) : "f"(x));
    return y;
}
__device__ __forceinline__ uint64_t pack2(float lo, float hi) {
    uint64_t r;
    asm("mov.b64 %0, {%1, %2};" : "=l"(r) : "f"(lo), "f"(hi));
    return r;
}
__device__ __forceinline__ void unpack2(float& lo, float& hi, uint64_t v) {
    asm("mov.b64 {%0, %1}, %2;" : "=f"(lo), "=f"(hi) : "l"(v));
}
__device__ __forceinline__ void fma2(uint64_t& acc, uint64_t a, uint64_t b) {
    asm("fma.rn.f32x2 %0, %1, %2, %0;" : "+l"(acc) : "l"(a), "l"(b));
}
__device__ __forceinline__ uint64_t add2(uint64_t a, uint64_t b) {
    uint64_t r;
    asm("add.rn.f32x2 %0, %1, %2;" : "=l"(r) : "l"(a), "l"(b));
    return r;
}
__device__ __forceinline__ void bar_sync(int id, int cnt) {
    asm volatile("bar.sync %0, %1;" :: "r"(id), "r"(cnt) : "memory");
}
__device__ __forceinline__ uint32_t smem_u32(const void* p) {
    uint32_t a;
    asm("{ .reg .u64 t; cvta.to.shared.u64 t, %1; cvt.u32.u64 %0, t; }"
        : "=r"(a) : "l"(p));
    return a;
}

__global__ void init_kernel() {
    if (threadIdx.x < NB) g_prog[threadIdx.x] = 0;
}

// grid = 148 x 160.
//   blocks 0..31: LSTM scan. Warps 0-3 = gates (i,f,g,o), lane = hidden dim;
//     per-step sync = named bar 1 (128 threads). Warp 0's h buffer is a 64-slot
//     ring -> h history lands in smem for free. Warp 4 = mover: copies chunk
//     n-1 ring->g_hs while chunk n scans; syncs only at chunk boundaries.
//   blocks 32..147: persistent epilogue workers (warp 4 idles at syncs).
__global__ void __launch_bounds__(NT, 1) fused_kernel(
    const float* __restrict__ x,      // (B, S)
    const float* __restrict__ bos,    // (D)
    const float* __restrict__ W_in,   // (1, D)
    const float* __restrict__ b_in,   // (D)
    const float* __restrict__ Wx,     // (D, 4D)
    const float* __restrict__ Wh,     // (D, 4D)
    const float* __restrict__ b_lstm, // (4D)
    const float* __restrict__ W_out,  // (D, C)
    const float* __restrict__ b_out,  // (C)
    float* __restrict__ out)          // (B, S, C)
{
    const int bid = blockIdx.x;
    const int tid = threadIdx.x;

    if (bid < NB) {
        // ───────────────────────── scan block ─────────────────────────
        const int b = bid;

        __shared__ float4 gbuf[2][32];     // [parity][dim] = {i,f,g,o}
        __shared__ float  hring[64][ND];   // warp 0's h ring (2 chunks)  8 KB
        __shared__ float  hbuf[3][32];     // warps 1-3 private h

        if (tid < 128) {
            // ── scan warps ──
            const int w = tid >> 5;     // gate: 0=i 1=f 2=g 3=o
            const int l = tid & 31;     // hidden dim
            const int k = tid;          // gate column
            const bool sig = (w != 2);

            const float ws = sig ? 0.5f : 1.0f;
            uint64_t whp[16];
#pragma unroll
            for (int j = 0; j < 16; j++)
                whp[j] = pack2(ws * Wh[(2 * j) * NG + k],
                               ws * Wh[(2 * j + 1) * NG + k]);

            float u = 0.f, v = 0.f, z0 = 0.f;
#pragma unroll
            for (int d = 0; d < ND; d++) {
                float wx = Wx[d * NG + k];
                u  = fmaf(W_in[d], wx, u);
                v  = fmaf(b_in[d], wx, v);
                z0 = fmaf(bos[d],  wx, z0);
            }
            float bl = b_lstm[k];
            v  = ws * (v + bl);
            z0 = ws * (z0 + bl);
            u *= ws;

            // h store/read addresses: warp 0 walks the ring, others fixed
            const uint32_t ring0 = smem_u32(hring);
            uint32_t hw = (w == 0) ? (ring0 + 63 * (ND * 4) + l * 4)
                                   : (smem_u32(hbuf) + ((w - 1) * 32 + l) * 4);
            uint32_t hr = (w == 0) ? ring0 + 63 * (ND * 4)
                                   : smem_u32(hbuf) + (w - 1) * 128;

            asm volatile("st.shared.f32 [%0], %1;" :: "r"(hw), "f"(0.f) : "memory");

            float c = 0.f;
            float zbase = z0;
            const float* xb = x + (size_t)b * NS;
            bar_sync(1, 128);

            // P = gbuf parity, J = step position in chunk (both compile-time)
#define STEP(P, J) do {                                                      \
        float xn = __shfl_sync(0xffffffffu, xv, (J));                        \
        uint64_t hp[16];                                                     \
        _Pragma("unroll")                                                    \
        for (int j = 0; j < 8; j++)                                          \
            asm volatile("ld.shared.v2.u64 {%0,%1}, [%2];"                   \
                         : "=l"(hp[2 * j]), "=l"(hp[2 * j + 1])              \
                         : "r"(hr + j * 16));                                \
        uint64_t a0 = pack2(zbase, 0.f), a1 = pack2(0.f, 0.f);               \
        uint64_t a2 = pack2(0.f, 0.f),   a3 = pack2(0.f, 0.f);               \
        _Pragma("unroll")                                                    \
        for (int j = 0; j < 4; j++) {                                        \
            fma2(a0, hp[4 * j + 0], whp[4 * j + 0]);                         \
            fma2(a1, hp[4 * j + 1], whp[4 * j + 1]);                         \
            fma2(a2, hp[4 * j + 2], whp[4 * j + 2]);                         \
            fma2(a3, hp[4 * j + 3], whp[4 * j + 3]);                         \
        }                                                                    \
        float lo, hi;                                                        \
        unpack2(lo, hi, add2(add2(a0, a1), add2(a2, a3)));                   \
        float z = lo + hi;                                                   \
        float t = tanh_fast(z);                                              \
        float act = sig ? fmaf(0.5f, t, 0.5f) : t;                           \
        ((float*)&gbuf[(P)][l])[w] = act;                                    \
        zbase = fmaf(xn, u, v);                                              \
        bar_sync(1, 128);                                                    \
        float4 g4 = gbuf[(P)][l];                                            \
        c = fmaf(g4.y, c, g4.x * g4.z);                                      \
        float h = g4.w * tanh_fast(c);                                       \
        if (w == 0) {                                                        \
            uint32_t ws_ = ring0 + (((s0 + (J)) & 63) * (ND * 4));           \
            asm volatile("st.shared.f32 [%0], %1;"                           \
                         :: "r"(ws_ + l * 4), "f"(h) : "memory");            \
            hr = ws_;                                                        \
        } else {                                                             \
            asm volatile("st.shared.f32 [%0], %1;"                           \
                         :: "r"(hw), "f"(h) : "memory");                     \
        }                                                                    \
    } while (0)

            for (int n = 0; n < NCHUNK; n++) {
                const int s0 = n * CHUNK;
                const float xv = __ldg(xb + s0 + l);   // chunk's x in lane regs
#pragma unroll
                for (int jj = 0; jj < CHUNK; jj += 4) {
                    STEP(0, jj + 0);
                    STEP(1, jj + 1);
                    STEP(0, jj + 2);
                    STEP(1, jj + 3);
                }
                __syncthreads();                 // chunk boundary (incl. mover)
            }
#undef STEP
        } else {
            // ── mover warp (warp 4) ──
            const int l = tid - 128;
            float* hs_b = g_hs + (size_t)b * NS * ND;

            for (int n = 0; n < NCHUNK; n++) {
                if (n >= 1) {
                    // copy chunk n-1 from ring half ((n-1)&1) to g_hs
                    const float4* src =
                        (const float4*)&hring[((n - 1) & 1) * CHUNK][0];
                    float4* dst =
                        (float4*)(hs_b + (size_t)(n - 1) * CHUNK * ND);
#pragma unroll
                    for (int q = 0; q < 8; q++)
                        dst[l + 32 * q] = src[l + 32 * q];
                    if (l == 0) {
                        __threadfence();
                        asm volatile("st.global.release.gpu.s32 [%0], %1;"
                                     :: "l"(&g_prog[b]), "r"(n) : "memory");
                    }
                }
                __syncthreads();                 // chunk boundary
            }
            // final chunk (scan warps have exited; no barrier needed)
            {
                const float4* src =
                    (const float4*)&hring[((NCHUNK - 1) & 1) * CHUNK][0];
                float4* dst =
                    (float4*)(hs_b + (size_t)(NCHUNK - 1) * CHUNK * ND);
#pragma unroll
                for (int q = 0; q < 8; q++)
                    dst[l + 32 * q] = src[l + 32 * q];
                if (l == 0) {
                    __threadfence();
                    asm volatile("st.global.release.gpu.s32 [%0], %1;"
                                 :: "l"(&g_prog[b]), "r"(NCHUNK) : "memory");
                }
            }
        }
    } else {
        // ─────────────────────── worker block ───────────────────────
        const int wkr = bid - NB;
        __shared__ float tile[CHUNK * ND];       // 4 KB h tile

        const int c0 = tid, c1 = tid + 128;      // valid for tid < 128
        uint64_t wv0[16], wv1[16];
        float bias0 = 0.f, bias1 = 0.f;
        if (tid < 128) {
#pragma unroll
            for (int j = 0; j < 16; j++) {
                wv0[j] = pack2(W_out[(2 * j) * NC + c0], W_out[(2 * j + 1) * NC + c0]);
                wv1[j] = pack2(W_out[(2 * j) * NC + c1], W_out[(2 * j + 1) * NC + c1]);
            }
            bias0 = b_out[c0];
            bias1 = b_out[c1];
        }

        for (int i = wkr; i < NITEM; i += NWORK) {
            const int b     = i & (NB - 1);
            const int chunk = i >> 5;

            if (tid == 0) {
                int cur;
                do {
                    asm volatile("ld.acquire.gpu.global.s32 %0, [%1];"
                                 : "=r"(cur) : "l"(&g_prog[b]) : "memory");
                    if (cur > chunk) break;
                    __nanosleep(128);
                } while (true);
            }
            __syncthreads();                     // flag acquire -> tile loads

            const float* src = g_hs + ((size_t)b * NS + (size_t)chunk * CHUNK) * ND;
            if (tid < 128) {
#pragma unroll
                for (int q = 0; q < 2; q++)
                    ((float4*)tile)[tid + 128 * q] = ((const float4*)src)[tid + 128 * q];
            }
            __syncthreads();

            if (tid < 128) {
                float* orow = out + ((size_t)b * NS + (size_t)chunk * CHUNK) * NC;
#pragma unroll 2
                for (int r = 0; r < CHUNK; r++) {
                    const ulonglong2* hr = (const ulonglong2*)(tile + r * ND);
                    uint64_t p0 = pack2(bias0, 0.f), p1 = pack2(0.f, 0.f);
                    uint64_t q0 = pack2(bias1, 0.f), q1 = pack2(0.f, 0.f);
#pragma unroll
                    for (int j = 0; j < 8; j++) {
                        ulonglong2 hv = hr[j];
                        fma2(p0, hv.x, wv0[2 * j]);
                        fma2(p1, hv.y, wv0[2 * j + 1]);
                        fma2(q0, hv.x, wv1[2 * j]);
                        fma2(q1, hv.y, wv1[2 * j + 1]);
                    }
                    float lo, hi, r0, r1;
                    unpack2(lo, hi, add2(p0, p1)); r0 = lo + hi;
                    unpack2(lo, hi, add2(q0, q1)); r1 = lo + hi;
                    orow[(size_t)r * NC + c0] = r0;
                    orow[(size_t)r * NC + c1] = r1;
                }
            }
            __syncthreads();                     // tile reuse guard
        }
    }
}

extern "C" void kernel_launch(void* const* d_in, const int* in_sizes, int n_in,
                              void* d_out, int out_size)
{
    const float* x      = (const float*)d_in[0];
    const float* bos    = (const float*)d_in[1];
    const float* W_in   = (const float*)d_in[2];
    const float* b_in   = (const float*)d_in[3];
    const float* Wx     = (const float*)d_in[4];
    const float* Wh     = (const float*)d_in[5];
    const float* b_lstm = (const float*)d_in[6];
    const float* W_out  = (const float*)d_in[7];
    const float* b_out  = (const float*)d_in[8];

    init_kernel<<<1, 32>>>();
    fused_kernel<<<148, NT>>>(x, bos, W_in, b_in, Wx, Wh, b_lstm,
                              W_out, b_out, (float*)d_out);
}

// round 9
// speedup vs baseline: 1.2951x; 1.0144x over previous
#include <cuda_runtime.h>
#include <cstdint>

#define NB 32        // batch
#define NS 8192      // seq len
#define ND 32        // hidden dim
#define NG 128       // 4*ND gates
#define NC 256       // output cats
#define CHUNK 32     // steps per progress publish
#define NCHUNK (NS / CHUNK)        // 256
#define NWORK 116                  // worker blocks (148 - 32)
#define NITEM (NB * NCHUNK)        // 8192 work items
#define NT 160                     // threads per block (5 warps in scan blocks)
#define ROWB (ND * 4)              // 128 bytes per ring row
#define HALFB (CHUNK * ROWB)       // 4096 bytes per ring half

// h history (B, S, D) fp32 = 33.5 MB + progress flags
__device__ float g_hs[NB * NS * ND];
__device__ int   g_prog[NB];

__device__ __forceinline__ float tanh_fast(float x) {
    float y;
    asm("tanh.approx.f32 %0, %1;" : "=f"(y) : "f"(x));
    return y;
}
__device__ __forceinline__ uint64_t pack2(float lo, float hi) {
    uint64_t r;
    asm("mov.b64 %0, {%1, %2};" : "=l"(r) : "f"(lo), "f"(hi));
    return r;
}
__device__ __forceinline__ void unpack2(float& lo, float& hi, uint64_t v) {
    asm("mov.b64 {%0, %1}, %2;" : "=f"(lo), "=f"(hi) : "l"(v));
}
__device__ __forceinline__ void fma2(uint64_t& acc, uint64_t a, uint64_t b) {
    asm("fma.rn.f32x2 %0, %1, %2, %0;" : "+l"(acc) : "l"(a), "l"(b));
}
__device__ __forceinline__ uint64_t add2(uint64_t a, uint64_t b) {
    uint64_t r;
    asm("add.rn.f32x2 %0, %1, %2;" : "=l"(r) : "l"(a), "l"(b));
    return r;
}
__device__ __forceinline__ void bar_sync(int id, int cnt) {
    asm volatile("bar.sync %0, %1;" :: "r"(id), "r"(cnt) : "memory");
}
__device__ __forceinline__ uint32_t smem_u32(const void* p) {
    uint32_t a;
    asm("{ .reg .u64 t; cvta.to.shared.u64 t, %1; cvt.u32.u64 %0, t; }"
        : "=r"(a) : "l"(p));
    return a;
}

__global__ void init_kernel() {
    if (threadIdx.x < NB) g_prog[threadIdx.x] = 0;
}

// grid = 148 x 160.
//   blocks 0..31: LSTM scan. Warps 0-3 = gates (i,f,g,o), lane = hidden dim;
//     per-step sync = named bar 1 (128 threads). EVERY warp owns a private
//     64-slot h ring (uniform code, compile-time offsets, symmetric barrier
//     arrival); warp 0's ring is the mover's source. gbuf transposed
//     [parity][gate][dim]: conflict-free STS + 4 scalar LDS (f first).
//     Warp 4 = mover: copies chunk n-1 ring->g_hs while chunk n scans.
//   blocks 32..147: persistent epilogue workers.
__global__ void __launch_bounds__(NT, 1) fused_kernel(
    const float* __restrict__ x,      // (B, S)
    const float* __restrict__ bos,    // (D)
    const float* __restrict__ W_in,   // (1, D)
    const float* __restrict__ b_in,   // (D)
    const float* __restrict__ Wx,     // (D, 4D)
    const float* __restrict__ Wh,     // (D, 4D)
    const float* __restrict__ b_lstm, // (4D)
    const float* __restrict__ W_out,  // (D, C)
    const float* __restrict__ b_out,  // (C)
    float* __restrict__ out)          // (B, S, C)
{
    const int bid = blockIdx.x;
    const int tid = threadIdx.x;

    if (bid < NB) {
        // ───────────────────────── scan block ─────────────────────────
        const int b = bid;

        __shared__ float gbuf[2][4][32];     // [parity][gate][dim]  1 KB
        __shared__ float rings[4][64][ND];   // per-warp h rings    32 KB

        if (tid < 128) {
            // ── scan warps ──
            const int w = tid >> 5;     // gate: 0=i 1=f 2=g 3=o
            const int l = tid & 31;     // hidden dim
            const int k = tid;          // gate column
            const bool sig = (w != 2);

            const float ws = sig ? 0.5f : 1.0f;
            uint64_t whp[16];
#pragma unroll
            for (int j = 0; j < 16; j++)
                whp[j] = pack2(ws * Wh[(2 * j) * NG + k],
                               ws * Wh[(2 * j + 1) * NG + k]);

            float u = 0.f, v = 0.f, z0 = 0.f;
#pragma unroll
            for (int d = 0; d < ND; d++) {
                float wx = Wx[d * NG + k];
                u  = fmaf(W_in[d], wx, u);
                v  = fmaf(b_in[d], wx, v);
                z0 = fmaf(bos[d],  wx, z0);
            }
            float bl = b_lstm[k];
            v  = ws * (v + bl);
            z0 = ws * (z0 + bl);
            u *= ws;

            const uint32_t ringw = smem_u32(&rings[w][0][0]);
            const uint32_t gb    = smem_u32(gbuf);
            const uint32_t ga    = gb + (uint32_t)(w * 32 + l) * 4;  // act store
            const uint32_t gl    = gb + (uint32_t)l * 4;             // gate loads

            // zero slot 63 of own ring (read by chunk 0 step 0)
            asm volatile("st.shared.f32 [%0], %1;"
                         :: "r"(ringw + 63 * ROWB + l * 4), "f"(0.f) : "memory");

            float c = 0.f;
            float zbase = z0;
            const float* xb = x + (size_t)b * NS;
            float xv_cur = __ldg(xb + l);           // chunk 0's x

            // P = gbuf parity, J = step position in chunk (compile-time)
#define STEP(P, J) do {                                                      \
        float xn = __shfl_sync(0xffffffffu, xv, (J));                        \
        const uint32_t rda = ((J) == 0) ? rbp : rb + ((J) - 1) * ROWB;       \
        uint64_t hp[16];                                                     \
        _Pragma("unroll")                                                    \
        for (int j = 0; j < 8; j++)                                          \
            asm volatile("ld.shared.v2.u64 {%0,%1}, [%2];"                   \
                         : "=l"(hp[2 * j]), "=l"(hp[2 * j + 1])              \
                         : "r"(rda + j * 16));                               \
        uint64_t a0 = pack2(zbase, 0.f), a1 = pack2(0.f, 0.f);               \
        uint64_t a2 = pack2(0.f, 0.f),   a3 = pack2(0.f, 0.f);               \
        _Pragma("unroll")                                                    \
        for (int j = 0; j < 4; j++) {                                        \
            fma2(a0, hp[4 * j + 0], whp[4 * j + 0]);                         \
            fma2(a1, hp[4 * j + 1], whp[4 * j + 1]);                         \
            fma2(a2, hp[4 * j + 2], whp[4 * j + 2]);                         \
            fma2(a3, hp[4 * j + 3], whp[4 * j + 3]);                         \
        }                                                                    \
        float lo, hi;                                                        \
        unpack2(lo, hi, add2(add2(a0, a1), add2(a2, a3)));                   \
        float z = lo + hi;                                                   \
        float t = tanh_fast(z);                                              \
        float act = sig ? fmaf(0.5f, t, 0.5f) : t;                           \
        asm volatile("st.shared.f32 [%0], %1;"                               \
                     :: "r"(ga + (P) * 512), "f"(act) : "memory");           \
        zbase = fmaf(xn, u, v);                                              \
        bar_sync(1, 128);                                                    \
        float f_, i_, g_, o_;                                                \
        asm volatile("ld.shared.f32 %0, [%1];" : "=f"(f_)                    \
                     : "r"(gl + (P) * 512 + 128));                           \
        asm volatile("ld.shared.f32 %0, [%1];" : "=f"(i_)                    \
                     : "r"(gl + (P) * 512 + 0));                             \
        asm volatile("ld.shared.f32 %0, [%1];" : "=f"(g_)                    \
                     : "r"(gl + (P) * 512 + 256));                           \
        asm volatile("ld.shared.f32 %0, [%1];" : "=f"(o_)                    \
                     : "r"(gl + (P) * 512 + 384));                           \
        c = fmaf(f_, c, i_ * g_);                                            \
        float h = o_ * tanh_fast(c);                                         \
        asm volatile("st.shared.f32 [%0], %1;"                               \
                     :: "r"(rb + (J) * ROWB + l * 4), "f"(h) : "memory");    \
    } while (0)

            for (int n = 0; n < NCHUNK; n++) {
                const uint32_t rb  = ringw + (uint32_t)(n & 1) * HALFB;
                const uint32_t rbp = ringw + (uint32_t)((n & 1) ^ 1) * HALFB
                                   + 31 * ROWB;
                const float xv = xv_cur;
                // prefetch next chunk's x a full chunk ahead (wraps at end,
                // value unused)
                xv_cur = __ldg(xb + ((n + 1) & (NCHUNK - 1)) * CHUNK + l);
#pragma unroll
                for (int jj = 0; jj < CHUNK; jj += 4) {
                    STEP(0, jj + 0);
                    STEP(1, jj + 1);
                    STEP(0, jj + 2);
                    STEP(1, jj + 3);
                }
                __syncthreads();                 // chunk boundary (incl. mover)
            }
#undef STEP
        } else {
            // ── mover warp (warp 4) ──
            const int l = tid - 128;
            float* hs_b = g_hs + (size_t)b * NS * ND;

            for (int n = 0; n < NCHUNK; n++) {
                if (n >= 1) {
                    // copy chunk n-1 from warp 0's ring half ((n-1)&1)
                    const float4* src =
                        (const float4*)&rings[0][((n - 1) & 1) * CHUNK][0];
                    float4* dst =
                        (float4*)(hs_b + (size_t)(n - 1) * CHUNK * ND);
#pragma unroll
                    for (int q = 0; q < 8; q++)
                        dst[l + 32 * q] = src[l + 32 * q];
                    if (l == 0) {
                        __threadfence();
                        asm volatile("st.global.release.gpu.s32 [%0], %1;"
                                     :: "l"(&g_prog[b]), "r"(n) : "memory");
                    }
                }
                __syncthreads();                 // chunk boundary
            }
            // final chunk (scan warps have exited)
            {
                const float4* src =
                    (const float4*)&rings[0][((NCHUNK - 1) & 1) * CHUNK][0];
                float4* dst =
                    (float4*)(hs_b + (size_t)(NCHUNK - 1) * CHUNK * ND);
#pragma unroll
                for (int q = 0; q < 8; q++)
                    dst[l + 32 * q] = src[l + 32 * q];
                if (l == 0) {
                    __threadfence();
                    asm volatile("st.global.release.gpu.s32 [%0], %1;"
                                 :: "l"(&g_prog[b]), "r"(NCHUNK) : "memory");
                }
            }
        }
    } else {
        // ─────────────────────── worker block ───────────────────────
        const int wkr = bid - NB;
        __shared__ float tile[CHUNK * ND];       // 4 KB h tile

        const int c0 = tid, c1 = tid + 128;      // valid for tid < 128
        uint64_t wv0[16], wv1[16];
        float bias0 = 0.f, bias1 = 0.f;
        if (tid < 128) {
#pragma unroll
            for (int j = 0; j < 16; j++) {
                wv0[j] = pack2(W_out[(2 * j) * NC + c0], W_out[(2 * j + 1) * NC + c0]);
                wv1[j] = pack2(W_out[(2 * j) * NC + c1], W_out[(2 * j + 1) * NC + c1]);
            }
            bias0 = b_out[c0];
            bias1 = b_out[c1];
        }

        for (int i = wkr; i < NITEM; i += NWORK) {
            const int b     = i & (NB - 1);
            const int chunk = i >> 5;

            if (tid == 0) {
                int cur;
                do {
                    asm volatile("ld.acquire.gpu.global.s32 %0, [%1];"
                                 : "=r"(cur) : "l"(&g_prog[b]) : "memory");
                    if (cur > chunk) break;
                    __nanosleep(128);
                } while (true);
            }
            __syncthreads();                     // flag acquire -> tile loads

            const float* src = g_hs + ((size_t)b * NS + (size_t)chunk * CHUNK) * ND;
            if (tid < 128) {
#pragma unroll
                for (int q = 0; q < 2; q++)
                    ((float4*)tile)[tid + 128 * q] = ((const float4*)src)[tid + 128 * q];
            }
            __syncthreads();

            if (tid < 128) {
                float* orow = out + ((size_t)b * NS + (size_t)chunk * CHUNK) * NC;
#pragma unroll 2
                for (int r = 0; r < CHUNK; r++) {
                    const ulonglong2* hr = (const ulonglong2*)(tile + r * ND);
                    uint64_t p0 = pack2(bias0, 0.f), p1 = pack2(0.f, 0.f);
                    uint64_t q0 = pack2(bias1, 0.f), q1 = pack2(0.f, 0.f);
#pragma unroll
                    for (int j = 0; j < 8; j++) {
                        ulonglong2 hv = hr[j];
                        fma2(p0, hv.x, wv0[2 * j]);
                        fma2(p1, hv.y, wv0[2 * j + 1]);
                        fma2(q0, hv.x, wv1[2 * j]);
                        fma2(q1, hv.y, wv1[2 * j + 1]);
                    }
                    float lo, hi, r0, r1;
                    unpack2(lo, hi, add2(p0, p1)); r0 = lo + hi;
                    unpack2(lo, hi, add2(q0, q1)); r1 = lo + hi;
                    orow[(size_t)r * NC + c0] = r0;
                    orow[(size_t)r * NC + c1] = r1;
                }
            }
            __syncthreads();                     // tile reuse guard
        }
    }
}

extern "C" void kernel_launch(void* const* d_in, const int* in_sizes, int n_in,
                              void* d_out, int out_size)
{
    const float* x      = (const float*)d_in[0];
    const float* bos    = (const float*)d_in[1];
    const float* W_in   = (const float*)d_in[2];
    const float* b_in   = (const float*)d_in[3];
    const float* Wx     = (const float*)d_in[4];
    const float* Wh     = (const float*)d_in[5];
    const float* b_lstm = (const float*)d_in[6];
    const float* W_out  = (const float*)d_in[7];
    const float* b_out  = (const float*)d_in[8];

    init_kernel<<<1, 32>>>();
    fused_kernel<<<148, NT>>>(x, bos, W_in, b_in, Wx, Wh, b_lstm,
                              W_out, b_out, (float*)d_out);
}